// round 2
// baseline (speedup 1.0000x reference)
#include <cuda_runtime.h>
#include <cstdint>
#include <cstddef>

// Problem constants
#define BATCH 4
#define NQ    2048
#define NK    2048
#define EMB   512
#define NH    8
#define HD    64
#define NTOK  (BATCH * NQ)          // 8192
#define SPM_N (BATCH * NQ * NK)     // 16777216

// ---------------- device-global scratch (no allocations allowed) -------------
__device__ float g_qn [NTOK * EMB];
__device__ float g_kvn[NTOK * EMB];
__device__ float g_q  [NTOK * EMB];
__device__ float g_k  [NTOK * EMB];
__device__ float g_v  [NTOK * EMB];
__device__ float g_ctx[NTOK * EMB];
__device__ unsigned char g_kvm[BATCH * NK];
__device__ unsigned char g_spm[SPM_N];
__device__ int g_is_byte[2];

// ---------------- mask dtype sniff + canonicalization ------------------------
// bool tensors may arrive as 1-byte bool or as int32 {0,1}. If int32, every
// byte at offset %4 != 0 within the first 8192 bytes is zero; if 1-byte bool,
// ~half of those bytes are 1 (deterministic given fixed inputs).
__global__ void detect_mask_kernel(const unsigned char* kvm_raw,
                                   const unsigned char* spm_raw) {
    __shared__ int found[2];
    if (threadIdx.x == 0) { found[0] = 0; found[1] = 0; }
    __syncthreads();
    for (int i = threadIdx.x; i < 8192; i += blockDim.x) {
        if ((i & 3) != 0) {
            if (kvm_raw[i]) atomicOr(&found[0], 1);
            if (spm_raw[i]) atomicOr(&found[1], 1);
        }
    }
    __syncthreads();
    if (threadIdx.x == 0) { g_is_byte[0] = found[0]; g_is_byte[1] = found[1]; }
}

__global__ void expand_kv_kernel(const void* raw) {
    int i = blockIdx.x * blockDim.x + threadIdx.x;
    if (i < BATCH * NK) {
        unsigned char v = g_is_byte[0] ? (((const unsigned char*)raw)[i] != 0)
                                       : (((const int*)raw)[i] != 0);
        g_kvm[i] = v;
    }
}

__global__ void expand_sp_kernel(const void* raw) {
    int i = blockIdx.x * blockDim.x + threadIdx.x;
    if (i < SPM_N) {
        unsigned char v = g_is_byte[1] ? (((const unsigned char*)raw)[i] != 0)
                                       : (((const int*)raw)[i] != 0);
        g_spm[i] = v;
    }
}

// ---------------- LayerNorm: one block (128 threads) per 512-elem row --------
__global__ void lnorm_kernel(const float* __restrict__ x,
                             const float* __restrict__ g,
                             const float* __restrict__ b,
                             float* __restrict__ y) {
    __shared__ float red[8];
    int row = blockIdx.x;
    int t   = threadIdx.x;                       // 0..127
    float4 v = ((const float4*)(x + (size_t)row * EMB))[t];
    float s  = v.x + v.y + v.z + v.w;
    float s2 = v.x*v.x + v.y*v.y + v.z*v.z + v.w*v.w;
    #pragma unroll
    for (int o = 16; o > 0; o >>= 1) {
        s  += __shfl_xor_sync(0xffffffffu, s,  o);
        s2 += __shfl_xor_sync(0xffffffffu, s2, o);
    }
    if ((t & 31) == 0) { red[t >> 5] = s; red[4 + (t >> 5)] = s2; }
    __syncthreads();
    float tot  = red[0] + red[1] + red[2] + red[3];
    float tot2 = red[4] + red[5] + red[6] + red[7];
    float mu  = tot  * (1.0f / EMB);
    float var = tot2 * (1.0f / EMB) - mu * mu;
    float inv = rsqrtf(var + 1e-5f);
    float4 gg = ((const float4*)g)[t];
    float4 bb = ((const float4*)b)[t];
    float4 o;
    o.x = (v.x - mu) * inv * gg.x + bb.x;
    o.y = (v.y - mu) * inv * gg.y + bb.y;
    o.z = (v.z - mu) * inv * gg.z + bb.z;
    o.w = (v.w - mu) * inv * gg.w + bb.w;
    ((float4*)(y + (size_t)row * EMB))[t] = o;
}

// ---------------- Tiled fp32 GEMM: Y[M,512] = X[M,512] @ W[512,512] + bias ---
// BM=128, BN=64, BK=16, 256 threads, 8x4 per-thread tile.
__global__ void gemm_bias_kernel(const float* __restrict__ X,
                                 const float* __restrict__ W,
                                 const float* __restrict__ bias,
                                 float* __restrict__ Y) {
    const int BM = 128, BN = 64, BK = 16;
    __shared__ float As[BK][BM];   // transposed A tile
    __shared__ float Bs[BK][BN];
    int bm  = blockIdx.y * BM;
    int bn  = blockIdx.x * BN;
    int tid = threadIdx.x;
    int tr  = tid >> 4;            // 0..15 -> rows tr*8..+7
    int tc  = tid & 15;            // 0..15 -> cols tc*4..+3

    float acc[8][4];
    #pragma unroll
    for (int i = 0; i < 8; i++)
        #pragma unroll
        for (int j = 0; j < 4; j++) acc[i][j] = 0.0f;

    for (int k0 = 0; k0 < EMB; k0 += BK) {
        #pragma unroll
        for (int i = 0; i < 2; i++) {
            int s   = tid * 2 + i;            // 0..511 float4 slots (128x16)
            int row = s >> 2;
            int c4  = s & 3;
            float4 a = *(const float4*)(X + (size_t)(bm + row) * EMB + k0 + c4 * 4);
            As[c4*4+0][row] = a.x;
            As[c4*4+1][row] = a.y;
            As[c4*4+2][row] = a.z;
            As[c4*4+3][row] = a.w;
        }
        {
            int row = tid >> 4;               // 0..15
            int c4  = tid & 15;               // 0..15
            *(float4*)&Bs[row][c4*4] =
                *(const float4*)(W + (size_t)(k0 + row) * EMB + bn + c4 * 4);
        }
        __syncthreads();
        #pragma unroll
        for (int kk = 0; kk < BK; kk++) {
            float a[8], bf[4];
            #pragma unroll
            for (int i = 0; i < 8; i++) a[i] = As[kk][tr * 8 + i];
            #pragma unroll
            for (int j = 0; j < 4; j++) bf[j] = Bs[kk][tc * 4 + j];
            #pragma unroll
            for (int i = 0; i < 8; i++)
                #pragma unroll
                for (int j = 0; j < 4; j++) acc[i][j] += a[i] * bf[j];
        }
        __syncthreads();
    }

    float4 bb = *(const float4*)(bias + bn + tc * 4);
    #pragma unroll
    for (int i = 0; i < 8; i++) {
        float4 o;
        o.x = acc[i][0] + bb.x;
        o.y = acc[i][1] + bb.y;
        o.z = acc[i][2] + bb.z;
        o.w = acc[i][3] + bb.w;
        *(float4*)(Y + (size_t)(bm + tr * 8 + i) * EMB + bn + tc * 4) = o;
    }
}

// ---------------- Fused flash attention (fp32, streaming online softmax) -----
// Block: (b, h, 64-query tile), 256 threads. Thread t: row r=t/4, sub=t&3.
// Per tile of 64 keys: scores for keys [sub*16, sub*16+16), online softmax
// across 4 lanes (shfl), P stored per-warp in smem, PV over d-slice sub*16..+15.
#define PPAD 68   // padded row stride (floats), 16B-aligned, bank-friendly
__global__ void attn_kernel(const float* __restrict__ Qp,
                            const float* __restrict__ Kp,
                            const float* __restrict__ Vp,
                            float* __restrict__ ctx) {
    extern __shared__ float sm[];
    float* Qs  = sm;                 // [64][PPAD]  Q[r][d]
    float* Kst = sm + 64 * PPAD;     // [64][PPAD]  K^T: [d][key]
    float* Vs  = sm + 2 * 64 * PPAD; // [64][PPAD]  V[key][d]
    float* Ps  = sm + 3 * 64 * PPAD; // [64][PPAD]  P[r][key]

    int qt  = blockIdx.x;            // 0..31
    int h   = blockIdx.y;            // 0..7
    int b   = blockIdx.z;            // 0..3
    int tid = threadIdx.x;
    int r   = tid >> 2;              // 0..63
    int sub = tid & 3;               // 0..3
    int q_global = qt * 64 + r;

    // load Q tile [64 rows x 64 dims]
    #pragma unroll
    for (int i = 0; i < 4; i++) {
        int s   = tid + i * 256;     // 1024 float4 slots
        int row = s >> 4;
        int d4  = s & 15;
        float4 v = *(const float4*)(Qp + (size_t)(b * NQ + qt * 64 + row) * EMB + h * HD + d4 * 4);
        *(float4*)&Qs[row * PPAD + d4 * 4] = v;
    }

    float m = -1e30f, l = 0.0f;
    float acc[16];
    #pragma unroll
    for (int i = 0; i < 16; i++) acc[i] = 0.0f;

    const unsigned char* kvm = g_kvm + b * NK;
    const unsigned char* spm = g_spm + ((size_t)b * NQ + q_global) * NK;
    const float scale = 0.125f;      // 64^-0.5
    const int kbase = sub * 16;
    const int dbase = sub * 16;

    for (int k0 = 0; k0 < NK; k0 += 64) {
        __syncthreads();             // prev tile reads done before overwrite
        // load K (transposed) and V tiles
        #pragma unroll
        for (int i = 0; i < 4; i++) {
            int s   = tid + i * 256;
            int key = s >> 4;
            int d4  = s & 15;
            size_t base = (size_t)(b * NK + k0 + key) * EMB + h * HD + d4 * 4;
            float4 kv4 = *(const float4*)(Kp + base);
            Kst[(d4*4+0) * PPAD + key] = kv4.x;
            Kst[(d4*4+1) * PPAD + key] = kv4.y;
            Kst[(d4*4+2) * PPAD + key] = kv4.z;
            Kst[(d4*4+3) * PPAD + key] = kv4.w;
            float4 vv = *(const float4*)(Vp + base);
            *(float4*)&Vs[key * PPAD + d4 * 4] = vv;
        }
        __syncthreads();

        // scores: this thread's 16 keys for its row
        float s16[16];
        #pragma unroll
        for (int j = 0; j < 16; j++) s16[j] = 0.0f;
        #pragma unroll 8
        for (int d = 0; d < HD; d++) {
            float qd = Qs[r * PPAD + d];
            const float* krow = &Kst[d * PPAD + kbase];
            #pragma unroll
            for (int j = 0; j < 16; j++) s16[j] += qd * krow[j];
        }

        // mask + scale + tile max
        float tmax = -1e30f;
        #pragma unroll
        for (int j = 0; j < 16; j++) {
            int k = k0 + kbase + j;
            bool valid = (kvm[k] != 0) && (spm[k] != 0);
            s16[j] = valid ? s16[j] * scale : -1e30f;
            tmax = fmaxf(tmax, s16[j]);
        }
        tmax = fmaxf(tmax, __shfl_xor_sync(0xffffffffu, tmax, 1));
        tmax = fmaxf(tmax, __shfl_xor_sync(0xffffffffu, tmax, 2));

        float mnew = fmaxf(m, tmax);
        float corr = __expf(m - mnew);   // both -1e30 -> exp(0)=1, acc is 0 anyway
        float psum = 0.0f;
        #pragma unroll
        for (int j = 0; j < 16; j++) {
            float p = (s16[j] > -1e29f) ? __expf(s16[j] - mnew) : 0.0f;
            s16[j] = p;
            psum += p;
        }
        psum += __shfl_xor_sync(0xffffffffu, psum, 1);
        psum += __shfl_xor_sync(0xffffffffu, psum, 2);
        l = l * corr + psum;
        m = mnew;
        #pragma unroll
        for (int i = 0; i < 16; i++) acc[i] *= corr;

        // stage P (only same-warp lanes read it: rows 0..7 of each warp)
        #pragma unroll
        for (int j = 0; j < 16; j += 4)
            *(float4*)&Ps[r * PPAD + kbase + j] =
                make_float4(s16[j], s16[j+1], s16[j+2], s16[j+3]);
        __syncwarp();

        // PV: acc[dbase..dbase+15] += sum_k P[r][k] * V[k][d]
        #pragma unroll 8
        for (int k = 0; k < 64; k++) {
            float p = Ps[r * PPAD + k];
            const float* vrow = &Vs[k * PPAD + dbase];
            #pragma unroll
            for (int j = 0; j < 16; j++) acc[j] += p * vrow[j];
        }
        __syncwarp();
    }

    float invl = (l > 0.0f) ? (1.0f / l) : 0.0f;
    float* op = ctx + (size_t)(b * NQ + q_global) * EMB + h * HD + dbase;
    #pragma unroll
    for (int j = 0; j < 16; j += 4)
        *(float4*)(op + j) = make_float4(acc[j] * invl, acc[j+1] * invl,
                                         acc[j+2] * invl, acc[j+3] * invl);
}

// ---------------- launch ------------------------------------------------------
extern "C" void kernel_launch(void* const* d_in, const int* in_sizes, int n_in,
                              void* d_out, int out_size) {
    const float* query     = (const float*)d_in[0];
    const float* key_value = (const float*)d_in[1];
    const void*  kvm_raw   = d_in[2];
    const void*  spm_raw   = d_in[3];
    const float* ln_q_g    = (const float*)d_in[4];
    const float* ln_q_b    = (const float*)d_in[5];
    const float* ln_kv_g   = (const float*)d_in[6];
    const float* ln_kv_b   = (const float*)d_in[7];
    const float* Wq = (const float*)d_in[8];
    const float* bq = (const float*)d_in[9];
    const float* Wk = (const float*)d_in[10];
    const float* bk = (const float*)d_in[11];
    const float* Wv = (const float*)d_in[12];
    const float* bv = (const float*)d_in[13];
    const float* Wo = (const float*)d_in[14];
    const float* bo = (const float*)d_in[15];
    float* out = (float*)d_out;

    void *p_qn, *p_kvn, *p_q, *p_k, *p_v, *p_ctx;
    cudaGetSymbolAddress(&p_qn,  g_qn);
    cudaGetSymbolAddress(&p_kvn, g_kvn);
    cudaGetSymbolAddress(&p_q,   g_q);
    cudaGetSymbolAddress(&p_k,   g_k);
    cudaGetSymbolAddress(&p_v,   g_v);
    cudaGetSymbolAddress(&p_ctx, g_ctx);

    // masks
    detect_mask_kernel<<<1, 256>>>((const unsigned char*)kvm_raw,
                                   (const unsigned char*)spm_raw);
    expand_kv_kernel<<<(BATCH * NK + 255) / 256, 256>>>(kvm_raw);
    expand_sp_kernel<<<SPM_N / 256, 256>>>(spm_raw);

    // layernorms
    lnorm_kernel<<<NTOK, 128>>>(query,     ln_q_g,  ln_q_b,  (float*)p_qn);
    lnorm_kernel<<<NTOK, 128>>>(key_value, ln_kv_g, ln_kv_b, (float*)p_kvn);

    // Q/K/V projections
    dim3 ggrid(EMB / 64, NTOK / 128);
    gemm_bias_kernel<<<ggrid, 256>>>((const float*)p_qn,  Wq, bq, (float*)p_q);
    gemm_bias_kernel<<<ggrid, 256>>>((const float*)p_kvn, Wk, bk, (float*)p_k);
    gemm_bias_kernel<<<ggrid, 256>>>((const float*)p_kvn, Wv, bv, (float*)p_v);

    // fused attention
    int smem_bytes = 4 * 64 * PPAD * (int)sizeof(float);   // 69632
    cudaFuncSetAttribute(attn_kernel,
                         cudaFuncAttributeMaxDynamicSharedMemorySize, smem_bytes);
    dim3 agrid(NQ / 64, NH, BATCH);
    attn_kernel<<<agrid, 256, smem_bytes>>>((const float*)p_q, (const float*)p_k,
                                            (const float*)p_v, (float*)p_ctx);

    // output projection
    gemm_bias_kernel<<<ggrid, 256>>>((const float*)p_ctx, Wo, bo, out);
}

// round 4
// speedup vs baseline: 5.4393x; 5.4393x over previous
#include <cuda_runtime.h>
#include <cstdint>
#include <cstddef>

#define BATCH 4
#define NQ    2048
#define NK    2048
#define EMB   512
#define NH    8
#define HD    64
#define NTOK  (BATCH * NQ)
#define BHN   (BATCH * NH)
#define SPM_N (BATCH * NQ * NK)

// ---------------- device-global scratch --------------------------------------
__device__ float g_qn [NTOK * EMB];
__device__ float g_kvn[NTOK * EMB];
__device__ float g_q  [NTOK * EMB];
__device__ float g_k  [NTOK * EMB];
__device__ float g_v  [NTOK * EMB];
__device__ float g_vt [BHN * HD * NK];
__device__ float g_ctx[NTOK * EMB];
__device__ float g_wt [4 * EMB * EMB];
__device__ float g_S  [(size_t)BHN * NQ * NK];
__device__ unsigned char g_kvm[BATCH * NK];
__device__ unsigned char g_spm[SPM_N];
__device__ int g_is_byte[2];

// ---------------- helpers -----------------------------------------------------
__device__ __forceinline__ float tf32r(float x) {
    uint32_t u;
    asm("cvt.rna.tf32.f32 %0, %1;" : "=r"(u) : "f"(x));
    return __uint_as_float(u);
}

#define MMA_TF32(C, A, B) \
    asm volatile( \
        "mma.sync.aligned.m16n8k8.row.col.f32.tf32.tf32.f32 " \
        "{%0,%1,%2,%3}, {%4,%5,%6,%7}, {%8,%9}, {%0,%1,%2,%3};" \
        : "+f"((C)[0]), "+f"((C)[1]), "+f"((C)[2]), "+f"((C)[3]) \
        : "r"((A)[0]), "r"((A)[1]), "r"((A)[2]), "r"((A)[3]), \
          "r"((B)[0]), "r"((B)[1]))

// ---------------- core tf32 GEMM: C[128 x NT] = A[128,K] * B[NT,K]^T ----------
// A row-major (lda), B stored [n][k] (ldb). 256 threads, 8 warps (4M x 2N).
// Warp tile 32 x (NT/2). BK=32, NC chunks. smem row stride 36 (pad).
template<int NT, int NC>
__device__ __forceinline__ void gemm_core(
        const float* __restrict__ A, size_t lda,
        const float* __restrict__ B, size_t ldb,
        float* __restrict__ C, size_t ldc,
        const float* __restrict__ bias) {
    extern __shared__ float smf[];
    float (*As)[36] = (float(*)[36])smf;
    float (*Bs)[36] = (float(*)[36])(smf + 128 * 36);

    const int tid  = threadIdx.x;
    const int lane = tid & 31, wid = tid >> 5;
    const int wm = wid & 3, wn = wid >> 2;
    const int g = lane >> 2, t = lane & 3;
    constexpr int NTW = NT / 16;       // n8 tiles per warp
    constexpr int NBF = NT / 32;       // B float4 fetches per thread

    float c[2][NTW][4];
    #pragma unroll
    for (int mt = 0; mt < 2; mt++)
        #pragma unroll
        for (int nt = 0; nt < NTW; nt++)
            #pragma unroll
            for (int j = 0; j < 4; j++) c[mt][nt][j] = 0.0f;

    float4 pa[4], pb[NBF];
    // prefetch chunk 0
    #pragma unroll
    for (int i = 0; i < 4; i++) {
        int s = tid + i * 256, r = s >> 3, f = s & 7;
        pa[i] = *(const float4*)(A + (size_t)r * lda + f * 4);
    }
    #pragma unroll
    for (int i = 0; i < NBF; i++) {
        int s = tid + i * 256, r = s >> 3, f = s & 7;
        pb[i] = *(const float4*)(B + (size_t)r * ldb + f * 4);
    }

    for (int ch = 0; ch < NC; ch++) {
        // store prefetched chunk to smem (with tf32 rounding)
        #pragma unroll
        for (int i = 0; i < 4; i++) {
            int s = tid + i * 256, r = s >> 3, f = s & 7;
            float4 v = pa[i];
            v.x = tf32r(v.x); v.y = tf32r(v.y);
            v.z = tf32r(v.z); v.w = tf32r(v.w);
            *(float4*)&As[r][f * 4] = v;
        }
        #pragma unroll
        for (int i = 0; i < NBF; i++) {
            int s = tid + i * 256, r = s >> 3, f = s & 7;
            float4 v = pb[i];
            v.x = tf32r(v.x); v.y = tf32r(v.y);
            v.z = tf32r(v.z); v.w = tf32r(v.w);
            *(float4*)&Bs[r][f * 4] = v;
        }
        __syncthreads();

        // prefetch next chunk (overlaps compute)
        if (ch + 1 < NC) {
            int co = (ch + 1) * 32;
            #pragma unroll
            for (int i = 0; i < 4; i++) {
                int s = tid + i * 256, r = s >> 3, f = s & 7;
                pa[i] = *(const float4*)(A + (size_t)r * lda + co + f * 4);
            }
            #pragma unroll
            for (int i = 0; i < NBF; i++) {
                int s = tid + i * 256, r = s >> 3, f = s & 7;
                pb[i] = *(const float4*)(B + (size_t)r * ldb + co + f * 4);
            }
        }

        // compute: 4 k-steps of 8
        #pragma unroll
        for (int ks = 0; ks < 4; ks++) {
            int k = ks * 8;
            uint32_t a[2][4];
            #pragma unroll
            for (int mt = 0; mt < 2; mt++) {
                int r = wm * 32 + mt * 16 + g;
                a[mt][0] = __float_as_uint(As[r][k + t]);
                a[mt][1] = __float_as_uint(As[r + 8][k + t]);
                a[mt][2] = __float_as_uint(As[r][k + t + 4]);
                a[mt][3] = __float_as_uint(As[r + 8][k + t + 4]);
            }
            uint32_t b[NTW][2];
            #pragma unroll
            for (int nt = 0; nt < NTW; nt++) {
                int n = wn * (NT / 2) + nt * 8 + g;
                b[nt][0] = __float_as_uint(Bs[n][k + t]);
                b[nt][1] = __float_as_uint(Bs[n][k + t + 4]);
            }
            #pragma unroll
            for (int mt = 0; mt < 2; mt++)
                #pragma unroll
                for (int nt = 0; nt < NTW; nt++)
                    MMA_TF32(c[mt][nt], a[mt], b[nt]);
        }
        __syncthreads();
    }

    // epilogue
    #pragma unroll
    for (int mt = 0; mt < 2; mt++) {
        #pragma unroll
        for (int nt = 0; nt < NTW; nt++) {
            int m   = wm * 32 + mt * 16 + g;
            int col = wn * (NT / 2) + nt * 8 + t * 2;
            float bx = 0.0f, by = 0.0f;
            if (bias) { bx = bias[col]; by = bias[col + 1]; }
            float2 v0 = make_float2(c[mt][nt][0] + bx, c[mt][nt][1] + by);
            float2 v1 = make_float2(c[mt][nt][2] + bx, c[mt][nt][3] + by);
            *(float2*)(C + (size_t)m * ldc + col)       = v0;
            *(float2*)(C + (size_t)(m + 8) * ldc + col) = v1;
        }
    }
}

__global__ void __launch_bounds__(256) proj_kernel(
        const float* __restrict__ X, const float* __restrict__ Wt,
        const float* __restrict__ bias, float* __restrict__ Y) {
    size_t bm = (size_t)blockIdx.y * 128, bn = (size_t)blockIdx.x * 128;
    gemm_core<128, 16>(X + bm * EMB, EMB, Wt + bn * EMB, EMB,
                       Y + bm * EMB + bn, EMB, bias + bn);
}

__global__ void __launch_bounds__(256) scores_kernel(
        const float* __restrict__ Qp, const float* __restrict__ Kp,
        float* __restrict__ S) {
    int kt = blockIdx.x, qt = blockIdx.y, bh = blockIdx.z;
    int b = bh >> 3, h = bh & 7;
    gemm_core<128, 2>(Qp + ((size_t)(b * NQ + qt * 128)) * EMB + h * HD, EMB,
                      Kp + ((size_t)(b * NK + kt * 128)) * EMB + h * HD, EMB,
                      S + ((size_t)bh * NQ + (size_t)qt * 128) * NK + (size_t)kt * 128,
                      NK, nullptr);
}

__global__ void __launch_bounds__(256) pv_kernel(
        const float* __restrict__ P, const float* __restrict__ Vt,
        float* __restrict__ ctx) {
    int qt = blockIdx.x, bh = blockIdx.y;
    int b = bh >> 3, h = bh & 7;
    gemm_core<64, 64>(P + ((size_t)bh * NQ + (size_t)qt * 128) * NK, NK,
                      Vt + (size_t)bh * HD * NK, NK,
                      ctx + ((size_t)(b * NQ + qt * 128)) * EMB + h * HD,
                      EMB, nullptr);
}

// ---------------- masks -------------------------------------------------------
__global__ void detect_mask_kernel(const unsigned char* kvm_raw,
                                   const unsigned char* spm_raw) {
    __shared__ int found[2];
    if (threadIdx.x == 0) { found[0] = 0; found[1] = 0; }
    __syncthreads();
    for (int i = threadIdx.x; i < 8192; i += blockDim.x) {
        if ((i & 3) != 0) {
            if (kvm_raw[i]) atomicOr(&found[0], 1);
            if (spm_raw[i]) atomicOr(&found[1], 1);
        }
    }
    __syncthreads();
    if (threadIdx.x == 0) { g_is_byte[0] = found[0]; g_is_byte[1] = found[1]; }
}
__global__ void expand_kv_kernel(const void* raw) {
    int i = blockIdx.x * blockDim.x + threadIdx.x;
    if (i < BATCH * NK)
        g_kvm[i] = g_is_byte[0] ? (((const unsigned char*)raw)[i] != 0)
                                : (((const int*)raw)[i] != 0);
}
__global__ void expand_sp_kernel(const void* raw) {
    int i = blockIdx.x * blockDim.x + threadIdx.x;
    g_spm[i] = g_is_byte[1] ? (((const unsigned char*)raw)[i] != 0)
                            : (((const int*)raw)[i] != 0);
}

// ---------------- LayerNorm ---------------------------------------------------
__global__ void lnorm_kernel(const float* __restrict__ x,
                             const float* __restrict__ g,
                             const float* __restrict__ b,
                             float* __restrict__ y) {
    __shared__ float red[8];
    int row = blockIdx.x, t = threadIdx.x;
    float4 v = ((const float4*)(x + (size_t)row * EMB))[t];
    float s  = v.x + v.y + v.z + v.w;
    float s2 = v.x*v.x + v.y*v.y + v.z*v.z + v.w*v.w;
    #pragma unroll
    for (int o = 16; o > 0; o >>= 1) {
        s  += __shfl_xor_sync(0xffffffffu, s,  o);
        s2 += __shfl_xor_sync(0xffffffffu, s2, o);
    }
    if ((t & 31) == 0) { red[t >> 5] = s; red[4 + (t >> 5)] = s2; }
    __syncthreads();
    float tot  = red[0] + red[1] + red[2] + red[3];
    float tot2 = red[4] + red[5] + red[6] + red[7];
    float mu  = tot * (1.0f / EMB);
    float var = tot2 * (1.0f / EMB) - mu * mu;
    float inv = rsqrtf(var + 1e-5f);
    float4 gg = ((const float4*)g)[t];
    float4 bb = ((const float4*)b)[t];
    float4 o;
    o.x = (v.x - mu) * inv * gg.x + bb.x;
    o.y = (v.y - mu) * inv * gg.y + bb.y;
    o.z = (v.z - mu) * inv * gg.z + bb.z;
    o.w = (v.w - mu) * inv * gg.w + bb.w;
    ((float4*)(y + (size_t)row * EMB))[t] = o;
}

// ---------------- transposes --------------------------------------------------
__global__ void wt_kernel(const float* __restrict__ W, float* __restrict__ Wt) {
    __shared__ float tile[32][33];
    int bx = blockIdx.x * 32, by = blockIdx.y * 32;
    int tx = threadIdx.x, ty = threadIdx.y;
    #pragma unroll
    for (int i = 0; i < 4; i++)
        tile[ty + i * 8][tx] = W[(size_t)(by + ty + i * 8) * EMB + bx + tx];
    __syncthreads();
    #pragma unroll
    for (int i = 0; i < 4; i++)
        Wt[(size_t)(bx + ty + i * 8) * EMB + by + tx] = tile[tx][ty + i * 8];
}
__global__ void vt_kernel() {
    __shared__ float tile[32][33];
    int kt = blockIdx.x * 32, dt = blockIdx.y * 32, bh = blockIdx.z;
    int b = bh >> 3, h = bh & 7;
    int tx = threadIdx.x, ty = threadIdx.y;
    #pragma unroll
    for (int i = 0; i < 4; i++)
        tile[ty + i * 8][tx] =
            g_v[(size_t)(b * NK + kt + ty + i * 8) * EMB + h * HD + dt + tx];
    __syncthreads();
    #pragma unroll
    for (int i = 0; i < 4; i++)
        g_vt[(size_t)(bh * HD + dt + ty + i * 8) * NK + kt + tx] =
            tile[tx][ty + i * 8];
}

// ---------------- masked softmax (in place on g_S) -----------------------------
__global__ void __launch_bounds__(256) softmax_kernel() {
    __shared__ float red[8];
    size_t row = blockIdx.x;
    int bh = (int)(row >> 11), q = (int)(row & 2047);
    int b = bh >> 3;
    float* Srow = g_S + row * NK;
    const unsigned char* kv = g_kvm + b * NK;
    const unsigned char* sp = g_spm + ((size_t)(b * NQ + q)) * NK;
    int t = threadIdx.x, k0 = t * 8;

    float4 a0 = *(float4*)(Srow + k0);
    float4 a1 = *(float4*)(Srow + k0 + 4);
    uint64_t mk = (*(const uint64_t*)(kv + k0)) & (*(const uint64_t*)(sp + k0));
    float s[8] = {a0.x, a0.y, a0.z, a0.w, a1.x, a1.y, a1.z, a1.w};
    float mx = -1e30f;
    #pragma unroll
    for (int j = 0; j < 8; j++) {
        bool v = ((mk >> (8 * j)) & 0xffULL) != 0;
        s[j] = v ? s[j] * 0.125f : -1e30f;
        mx = fmaxf(mx, s[j]);
    }
    #pragma unroll
    for (int o = 16; o > 0; o >>= 1)
        mx = fmaxf(mx, __shfl_xor_sync(0xffffffffu, mx, o));
    if ((t & 31) == 0) red[t >> 5] = mx;
    __syncthreads();
    mx = fmaxf(fmaxf(fmaxf(red[0], red[1]), fmaxf(red[2], red[3])),
               fmaxf(fmaxf(red[4], red[5]), fmaxf(red[6], red[7])));

    float sum = 0.0f;
    #pragma unroll
    for (int j = 0; j < 8; j++) {
        float p = (s[j] > -1e29f) ? __expf(s[j] - mx) : 0.0f;
        s[j] = p;
        sum += p;
    }
    #pragma unroll
    for (int o = 16; o > 0; o >>= 1)
        sum += __shfl_xor_sync(0xffffffffu, sum, o);
    __syncthreads();
    if ((t & 31) == 0) red[t >> 5] = sum;
    __syncthreads();
    sum = red[0] + red[1] + red[2] + red[3] + red[4] + red[5] + red[6] + red[7];
    float invl = (sum > 0.0f) ? (1.0f / sum) : 0.0f;
    *(float4*)(Srow + k0)     = make_float4(s[0]*invl, s[1]*invl, s[2]*invl, s[3]*invl);
    *(float4*)(Srow + k0 + 4) = make_float4(s[4]*invl, s[5]*invl, s[6]*invl, s[7]*invl);
}

// ---------------- launch ------------------------------------------------------
extern "C" void kernel_launch(void* const* d_in, const int* in_sizes, int n_in,
                              void* d_out, int out_size) {
    const float* query     = (const float*)d_in[0];
    const float* key_value = (const float*)d_in[1];
    const void*  kvm_raw   = d_in[2];
    const void*  spm_raw   = d_in[3];
    const float* ln_q_g  = (const float*)d_in[4];
    const float* ln_q_b  = (const float*)d_in[5];
    const float* ln_kv_g = (const float*)d_in[6];
    const float* ln_kv_b = (const float*)d_in[7];
    const float* Wq = (const float*)d_in[8];
    const float* bq = (const float*)d_in[9];
    const float* Wk = (const float*)d_in[10];
    const float* bk = (const float*)d_in[11];
    const float* Wv = (const float*)d_in[12];
    const float* bv = (const float*)d_in[13];
    const float* Wo = (const float*)d_in[14];
    const float* bo = (const float*)d_in[15];
    float* out = (float*)d_out;

    void *p_qn, *p_kvn, *p_q, *p_k, *p_v, *p_vt, *p_ctx, *p_wt, *p_S;
    cudaGetSymbolAddress(&p_qn,  g_qn);
    cudaGetSymbolAddress(&p_kvn, g_kvn);
    cudaGetSymbolAddress(&p_q,   g_q);
    cudaGetSymbolAddress(&p_k,   g_k);
    cudaGetSymbolAddress(&p_v,   g_v);
    cudaGetSymbolAddress(&p_vt,  g_vt);
    cudaGetSymbolAddress(&p_ctx, g_ctx);
    cudaGetSymbolAddress(&p_wt,  g_wt);
    cudaGetSymbolAddress(&p_S,   g_S);
    float* wt = (float*)p_wt;

    detect_mask_kernel<<<1, 256>>>((const unsigned char*)kvm_raw,
                                   (const unsigned char*)spm_raw);
    expand_kv_kernel<<<(BATCH * NK + 255) / 256, 256>>>(kvm_raw);
    expand_sp_kernel<<<SPM_N / 256, 256>>>(spm_raw);

    lnorm_kernel<<<NTOK, 128>>>(query,     ln_q_g,  ln_q_b,  (float*)p_qn);
    lnorm_kernel<<<NTOK, 128>>>(key_value, ln_kv_g, ln_kv_b, (float*)p_kvn);

    dim3 tb(32, 8), tg(16, 16);
    wt_kernel<<<tg, tb>>>(Wq, wt + 0 * EMB * EMB);
    wt_kernel<<<tg, tb>>>(Wk, wt + 1 * EMB * EMB);
    wt_kernel<<<tg, tb>>>(Wv, wt + 2 * EMB * EMB);
    wt_kernel<<<tg, tb>>>(Wo, wt + 3 * EMB * EMB);

    const int SMEM128 = (128 + 128) * 36 * 4;   // 36864
    const int SMEM64  = (128 + 64) * 36 * 4;    // 27648

    dim3 pg(EMB / 128, NTOK / 128);
    proj_kernel<<<pg, 256, SMEM128>>>((const float*)p_qn,
        wt + 0 * EMB * EMB, bq, (float*)p_q);
    proj_kernel<<<pg, 256, SMEM128>>>((const float*)p_kvn,
        wt + 1 * EMB * EMB, bk, (float*)p_k);
    proj_kernel<<<pg, 256, SMEM128>>>((const float*)p_kvn,
        wt + 2 * EMB * EMB, bv, (float*)p_v);

    dim3 vg(NK / 32, HD / 32, BHN);
    vt_kernel<<<vg, tb>>>();

    dim3 sg(NK / 128, NQ / 128, BHN);
    scores_kernel<<<sg, 256, SMEM128>>>((const float*)p_q, (const float*)p_k,
                                        (float*)p_S);
    softmax_kernel<<<BHN * NQ, 256>>>();

    dim3 pvg(NQ / 128, BHN);
    pv_kernel<<<pvg, 256, SMEM64>>>((const float*)p_S, (const float*)p_vt,
                                    (float*)p_ctx);

    proj_kernel<<<pg, 256, SMEM128>>>((const float*)p_ctx,
        wt + 3 * EMB * EMB, bo, out);
}